// round 7
// baseline (speedup 1.0000x reference)
#include <cuda_runtime.h>
#include <cuda_bf16.h>
#include <mma.h>

using namespace nvcuda;

#define Bsz   2
#define Cdim  192
#define Hdim  256
#define Wdim  256
#define HW    65536
#define CHW   12582912
#define NHEAD 6
#define HD    32
#define NTOK  131072
#define C3    576
#define HID   384
#define NWIN  2048

// ---------------- scratch (device globals; no allocation allowed) ----------------
__device__ __nv_bfloat16 g_roll[(size_t)Bsz*CHW];
__device__ __nv_bfloat16 g_win[(size_t)NTOK*Cdim];
__device__ __nv_bfloat16 g_qkv[(size_t)NTOK*C3];
__device__ __nv_bfloat16 g_attnout[(size_t)NTOK*Cdim];
__device__ __nv_bfloat16 g_yattn[(size_t)Bsz*CHW];
__device__ float         g_gappart[(size_t)Bsz*Cdim*512];
__device__ float         g_s[Bsz*Cdim];
__device__ __nv_bfloat16 g_t[(size_t)NTOK*Cdim];
__device__ __nv_bfloat16 g_h[(size_t)NTOK*HID];
__device__ __nv_bfloat16 g_wqkv[Cdim*C3];
__device__ float         g_bqkv[C3];
__device__ __nv_bfloat16 g_wproj[Cdim*Cdim];
__device__ __nv_bfloat16 g_wfc1[Cdim*HID];
__device__ __nv_bfloat16 g_wfc2[HID*Cdim];

// ---------------- all weight conversions in one kernel (scale folded into q cols) -------------
__global__ void k_conv_all(const float* __restrict__ qw, const float* __restrict__ qb,
                           const float* __restrict__ pw, const float* __restrict__ f1,
                           const float* __restrict__ f2){
    int i = blockIdx.x*256 + threadIdx.x;
    const float sc = 0.17677669529663687f; // 32^-0.5
    if (i < Cdim*C3){
        int o = i % C3;
        float f = qw[i];
        if (o < Cdim) f *= sc;
        g_wqkv[i] = __float2bfloat16(f);
    }
    if (i < C3){
        float f = qb[i];
        if (i < Cdim) f *= sc;
        g_bqkv[i] = f;
    }
    if (i < Cdim*Cdim) g_wproj[i] = __float2bfloat16(pw[i]);
    if (i < Cdim*HID)  g_wfc1[i]  = __float2bfloat16(f1[i]);
    if (i < HID*Cdim)  g_wfc2[i]  = __float2bfloat16(f2[i]);
}

// ---------------- norm1 (over C per pixel) fused with the "buggy" flat roll ----------------
__global__ void k_norm1_roll(const float* __restrict__ x,
                             const float* __restrict__ nw, const float* __restrict__ nb){
    __shared__ float tile[Cdim][33];
    __shared__ float red1[8][32], red2[8][32];
    __shared__ float s_mu[32], s_ri[32];
    __shared__ float s_w[Cdim], s_b[Cdim];
    int b = blockIdx.y;
    int p0 = blockIdx.x * 32;
    const float* xb = x + (size_t)b*CHW;
    int tid = threadIdx.x;
    if (tid < Cdim){ s_w[tid]=nw[tid]; s_b[tid]=nb[tid]; }
    #pragma unroll
    for (int it=0; it<24; it++){
        int idx = it*256+tid;
        int c = idx>>5, p = idx&31;
        tile[c][p] = xb[(size_t)c*HW + p0 + p];
    }
    __syncthreads();
    int p = tid&31, g = tid>>5;
    float sum=0.f, sq=0.f;
    for (int c=g; c<Cdim; c+=8){ float v=tile[c][p]; sum+=v; sq+=v*v; }
    red1[g][p]=sum; red2[g][p]=sq;
    __syncthreads();
    if (g==0){
        float s=0.f,q=0.f;
        #pragma unroll
        for (int k=0;k<8;k++){ s+=red1[k][p]; q+=red2[k][p]; }
        float mu = s*(1.f/Cdim);
        float var = q*(1.f/Cdim) - mu*mu;
        s_mu[p]=mu; s_ri[p]=rsqrtf(var+1e-6f);
    }
    __syncthreads();
    __nv_bfloat16* rb = g_roll + (size_t)b*CHW;
    #pragma unroll
    for (int it=0; it<24; it++){
        int idx = it*256+tid;
        int c = idx>>5, pp = idx&31;
        float v = (tile[c][pp]-s_mu[pp])*s_ri[pp]*s_w[c]+s_b[c];
        int f = c*HW + p0 + pp;
        int i = f/49152; int r = f - i*49152; int j = r/192; int k = r - j*192;
        int t = ((i-4)&255)*49152 + ((j-4)&255)*192 + k;
        rb[t] = __float2bfloat16(v);
    }
}

// ---------------- window partition: rolled BCHW -> (win, n, c) tokens ----------------
__global__ void k_win_gather(){
    __shared__ __nv_bfloat16 s[96][66];
    int wi = blockIdx.x; int tid = threadIdx.x;
    int b = wi>>10, gh=(wi&1023)>>5, gw=wi&31;
    const __nv_bfloat16* rb = g_roll + (size_t)b*CHW;
    size_t base = (size_t)(gh*8)*256 + gw*8;
    for (int chunk=0; chunk<2; chunk++){
        int c0 = chunk*96;
        #pragma unroll
        for (int it=0; it<24; it++){
            int idx = it*256+tid;
            int cl = idx>>6, n = idx&63;
            s[cl][n] = rb[(size_t)(c0+cl)*HW + base + (n>>3)*256 + (n&7)];
        }
        __syncthreads();
        #pragma unroll
        for (int it=0; it<24; it++){
            int idx = it*256+tid;
            int n = idx/96, cl = idx%96;
            g_win[((size_t)wi*64+n)*Cdim + c0 + cl] = s[cl][n];
        }
        __syncthreads();
    }
}

// ---------------- GEMM mainloop: 128x64 tile, resident B, double-buffered A -------------------
// returns smem pointer to Cs[128][68] (raw accum, pre-bias), after syncthreads.
template<int K, int N>
__device__ __forceinline__ float* gemm_main(const __nv_bfloat16* __restrict__ A,
                                            const __nv_bfloat16* __restrict__ Bm){
    extern __shared__ __align__(16) char sm[];
    __nv_bfloat16* Bs = (__nv_bfloat16*)sm;                       // [K][80]
    __nv_bfloat16* As = (__nv_bfloat16*)(sm + (size_t)K*80*2);    // [2][128][80]
    float*         Cs = (float*)(sm + (size_t)K*80*2);            // [128][68] (aliases As)
    const int tid = threadIdx.x;
    const int m0 = blockIdx.x*128, n0 = blockIdx.y*64;
    const int warp = tid>>5, wr = warp>>1, wc = warp&1;

    #pragma unroll
    for (int it=0; it<K/32; it++){
        int idx = it*256+tid;
        int row = idx>>3, u = idx&7;
        *(uint4*)&Bs[row*80 + u*8] = *(const uint4*)&Bm[(size_t)row*N + n0 + u*8];
    }
    auto loadA = [&](int c, int buf){
        #pragma unroll
        for (int it=0; it<4; it++){
            int idx = it*256+tid;
            int row = idx>>3, u = idx&7;
            *(uint4*)&As[(size_t)(buf*128+row)*80 + u*8] =
                *(const uint4*)&A[(size_t)(m0+row)*K + c*64 + u*8];
        }
    };
    loadA(0,0);
    wmma::fragment<wmma::accumulator,16,16,16,float> acc[2][2];
    #pragma unroll
    for (int i=0;i<2;i++)
        #pragma unroll
        for (int j=0;j<2;j++) wmma::fill_fragment(acc[i][j], 0.f);
    __syncthreads();

    constexpr int NC = K/64;
    #pragma unroll
    for (int c=0;c<NC;c++){
        if (c+1 < NC) loadA(c+1, (c+1)&1);
        int buf = c&1;
        #pragma unroll
        for (int kk=0;kk<64;kk+=16){
            wmma::fragment<wmma::matrix_a,16,16,16,__nv_bfloat16,wmma::row_major> af[2];
            wmma::fragment<wmma::matrix_b,16,16,16,__nv_bfloat16,wmma::row_major> bf[2];
            #pragma unroll
            for (int i=0;i<2;i++) wmma::load_matrix_sync(af[i], &As[(size_t)(buf*128+wr*32+i*16)*80 + kk], 80);
            #pragma unroll
            for (int j=0;j<2;j++) wmma::load_matrix_sync(bf[j], &Bs[(size_t)(c*64+kk)*80 + wc*32+j*16], 80);
            #pragma unroll
            for (int i=0;i<2;i++)
                #pragma unroll
                for (int j=0;j<2;j++)
                    wmma::mma_sync(acc[i][j], af[i], bf[j], acc[i][j]);
        }
        __syncthreads();
    }
    #pragma unroll
    for (int i=0;i<2;i++)
        #pragma unroll
        for (int j=0;j<2;j++)
            wmma::store_matrix_sync(&Cs[(size_t)(wr*32+i*16)*68 + wc*32+j*16], acc[i][j], 68, wmma::mem_row_major);
    __syncthreads();
    return Cs;
}

// qkv: plain bf16 epilogue
__global__ void __launch_bounds__(256) k_gemm_qkv(){
    float* Cs = gemm_main<Cdim,C3>(g_win, g_wqkv);
    const int tid = threadIdx.x;
    const int m0 = blockIdx.x*128, n0 = blockIdx.y*64;
    #pragma unroll
    for (int it=0; it<32; it++){
        int idx = it*256+tid;
        int r = idx>>6, cc = idx&63;
        float v = Cs[(size_t)r*68+cc] + g_bqkv[n0+cc];
        g_qkv[(size_t)(m0+r)*C3 + n0 + cc] = __float2bfloat16(v);
    }
}

// fc1: gelu epilogue
__global__ void __launch_bounds__(256) k_gemm_fc1(const float* __restrict__ bias){
    float* Cs = gemm_main<Cdim,HID>(g_t, g_wfc1);
    const int tid = threadIdx.x;
    const int m0 = blockIdx.x*128, n0 = blockIdx.y*64;
    #pragma unroll
    for (int it=0; it<32; it++){
        int idx = it*256+tid;
        int r = idx>>6, cc = idx&63;
        float v = Cs[(size_t)r*68+cc] + bias[n0+cc];
        v = 0.5f*v*(1.f+erff(v*0.70710678118654752f));
        g_h[(size_t)(m0+r)*HID + n0 + cc] = __float2bfloat16(v);
    }
}

// proj: fused window-reverse scatter into BCHW yattn + deterministic gap partials
__global__ void __launch_bounds__(256) k_gemm_proj_f(const float* __restrict__ bias){
    float* Cs = gemm_main<Cdim,Cdim>(g_attnout, g_wproj);
    __shared__ float sgap[4][64];
    const int tid = threadIdx.x;
    const int m0 = blockIdx.x*128, n0 = blockIdx.y*64;
    const int w0 = m0/64;                 // first window of the pair
    const int b  = w0>>10;
    // scatter: token (wi, n) -> pixel b,c,(gh*8+(n>>3))*256 + gw*8+(n&7)
    const int lane16 = tid&15, w = lane16>>3, q = lane16&7, grp16 = tid>>4;
    {
        int wi = w0 + w;
        int gh = (wi&1023)>>5, gw = wi&31;
        size_t pixbase = (size_t)b*CHW + (size_t)gh*2048 + gw*8 + q;
        #pragma unroll
        for (int it=0; it<32; it++){
            int combo = it*16 + grp16;      // 0..511 = cc*8 + i
            int cc = combo>>3, i = combo&7;
            int r = w*64 + i*8 + q;
            float v = Cs[(size_t)r*68+cc] + bias[n0+cc];
            g_yattn[pixbase + (size_t)(n0+cc)*HW + i*256] = __float2bfloat16(v);
        }
    }
    // gap partials (sum of bf16-rounded outputs per channel over this tile's 128 tokens)
    {
        int cc = tid&63, grp = tid>>6;
        float s = 0.f;
        float bb = bias[n0+cc];
        #pragma unroll
        for (int k=0;k<32;k++){
            int r = grp*32+k;
            s += __bfloat162float(__float2bfloat16(Cs[(size_t)r*68+cc] + bb));
        }
        sgap[grp][cc] = s;
        __syncthreads();
        if (tid < 64){
            float t = sgap[0][tid]+sgap[1][tid]+sgap[2][tid]+sgap[3][tid];
            g_gappart[(size_t)(b*Cdim + n0 + tid)*512 + (blockIdx.x & 511)] = t;
        }
    }
}

// fc2: fused final residual  out = x + yattn*s + fc2(h)
__global__ void __launch_bounds__(256) k_gemm_fc2_f(const float* __restrict__ bias,
                                                    const float* __restrict__ x,
                                                    float* __restrict__ out){
    float* Cs = gemm_main<HID,Cdim>(g_h, g_wfc2);
    __shared__ float s_sc[64];
    const int tid = threadIdx.x;
    const int m0 = blockIdx.x*128, n0 = blockIdx.y*64;
    const int b = m0>>16, p0 = m0&65535;
    if (tid < 64) s_sc[tid] = g_s[b*Cdim + n0 + tid];
    __syncthreads();
    #pragma unroll
    for (int it=0; it<32; it++){
        int idx = it*256+tid;
        int cc = idx>>7, pp = idx&127;
        float v = Cs[(size_t)pp*68+cc] + bias[n0+cc];
        size_t off = (size_t)b*CHW + (size_t)(n0+cc)*HW + p0 + pp;
        float y = __bfloat162float(g_yattn[off]);
        out[off] = x[off] + y*s_sc[cc] + v;
    }
}

// ---------------- fused window attention, WMMA: 2 blocks/SM (112.5KB smem) ----------------
#define LDQ 584
#define ATT_SS  74752
#define ATT_RPB 109568
#define ATT_CLS 112272
#define ATT_SM  112528
__global__ void __launch_bounds__(256) k_attn(const float* __restrict__ rpb){
    extern __shared__ __align__(16) char sm[];
    __nv_bfloat16* sQ   = (__nv_bfloat16*)sm;                   // [64][584]
    float*         sS   = (float*)(sm + ATT_SS);                // [8][16*68]  (P aliases this)
    __nv_bfloat16* sRpb = (__nv_bfloat16*)(sm + ATT_RPB);       // [6*225]
    int*           sCls = (int*)(sm + ATT_CLS);                 // [64]
    int wi = blockIdx.x;
    int tid = threadIdx.x, warp = tid>>5, lane = tid&31;
    int gh = (wi & 1023) >> 5, gw = wi & 31;

    const __nv_bfloat16* qkvb = g_qkv + (size_t)wi*64*C3;
    #pragma unroll
    for (int it=0; it<18; it++){
        int idx = it*256+tid;
        int row = idx/72, u = idx%72;
        *(uint4*)&sQ[row*LDQ + u*8] = *(const uint4*)&qkvb[(size_t)row*C3 + u*8];
    }
    for (int i=tid; i<NHEAD*225; i+=256){
        int h = i/225, p = i%225;
        sRpb[h*225+p] = __float2bfloat16(rpb[p*NHEAD + h]);
    }
    if (tid < 64){
        int i = tid>>3, j = tid&7;
        int hg = gh*8+i, wg = gw*8+j;
        int rh = hg < 248 ? 0 : (hg < 252 ? 1 : 2);
        int rw = wg < 248 ? 0 : (wg < 252 ? 1 : 2);
        sCls[tid] = rh*3+rw;
    }
    __syncthreads();

    #pragma unroll
    for (int r=0; r<3; r++){
        int task = warp + 8*r;            // 0..23
        int h = task>>2, strip = task&3, n0 = strip*16;
        float*         Sw = sS + warp*16*68;
        __nv_bfloat16* Pw = (__nv_bfloat16*)Sw;     // alias: reads complete before writes
        // ---- S = Q Kt (16x64) ----
        wmma::fragment<wmma::accumulator,16,16,16,float> acc[4];
        #pragma unroll
        for (int j=0;j<4;j++) wmma::fill_fragment(acc[j], 0.f);
        #pragma unroll
        for (int kk=0; kk<32; kk+=16){
            wmma::fragment<wmma::matrix_a,16,16,16,__nv_bfloat16,wmma::row_major> aq;
            wmma::load_matrix_sync(aq, &sQ[(size_t)n0*LDQ + h*HD + kk], LDQ);
            #pragma unroll
            for (int j=0;j<4;j++){
                wmma::fragment<wmma::matrix_b,16,16,16,__nv_bfloat16,wmma::col_major> bk;
                wmma::load_matrix_sync(bk, &sQ[(size_t)(j*16)*LDQ + Cdim + h*HD + kk], LDQ);
                wmma::mma_sync(acc[j], aq, bk, acc[j]);
            }
        }
        #pragma unroll
        for (int j=0;j<4;j++)
            wmma::store_matrix_sync(&Sw[j*16], acc[j], 68, wmma::mem_row_major);
        __syncwarp();
        // ---- softmax with rpb bias + shift mask (lane: one row half); read all -> regs first
        {
            int row = lane>>1, half = (lane&1)*32;
            int n = n0+row, ni = n>>3, nj = n&7;
            int cn = sCls[n];
            const __nv_bfloat16* rh = sRpb + h*225;
            float e[32]; float mx = -1e30f;
            #pragma unroll
            for (int c=0;c<32;c++){
                int m = half+c;
                float v = Sw[row*68+m] + __bfloat162float(rh[(ni-(m>>3)+7)*15 + (nj-(m&7)+7)]);
                if (cn != sCls[m]) v -= 100.f;
                e[c]=v; mx = fmaxf(mx, v);
            }
            mx = fmaxf(mx, __shfl_xor_sync(0xffffffffu, mx, 1));   // warp-sync: all reads done
            float sum = 0.f;
            #pragma unroll
            for (int c=0;c<32;c++){ e[c] = __expf(e[c]-mx); sum += e[c]; }
            sum += __shfl_xor_sync(0xffffffffu, sum, 1);
            float inv = 1.f/sum;
            __syncwarp();
            #pragma unroll
            for (int c=0;c<32;c++) Pw[row*72+half+c] = __float2bfloat16(e[c]*inv);
        }
        __syncwarp();
        // ---- out = P V (16x32) ----
        wmma::fragment<wmma::accumulator,16,16,16,float> acc2[2];
        #pragma unroll
        for (int j=0;j<2;j++) wmma::fill_fragment(acc2[j], 0.f);
        #pragma unroll
        for (int k4=0;k4<4;k4++){
            wmma::fragment<wmma::matrix_a,16,16,16,__nv_bfloat16,wmma::row_major> ap;
            wmma::load_matrix_sync(ap, &Pw[k4*16], 72);
            #pragma unroll
            for (int j=0;j<2;j++){
                wmma::fragment<wmma::matrix_b,16,16,16,__nv_bfloat16,wmma::row_major> bv;
                wmma::load_matrix_sync(bv, &sQ[(size_t)(k4*16)*LDQ + 2*Cdim + h*HD + j*16], LDQ);
                wmma::mma_sync(acc2[j], ap, bv, acc2[j]);
            }
        }
        __syncwarp();     // all Pw reads done before overwriting region
        #pragma unroll
        for (int j=0;j<2;j++)
            wmma::store_matrix_sync(&Sw[j*16], acc2[j], 36, wmma::mem_row_major);
        __syncwarp();
        {
            int row = lane>>1, halfo = (lane&1)*16;
            __nv_bfloat16* op = g_attnout + ((size_t)(wi*64 + n0+row))*Cdim + h*HD + halfo;
            #pragma unroll
            for (int c=0;c<16;c++) op[c] = __float2bfloat16(Sw[row*36 + halfo + c]);
        }
        __syncwarp();
    }
}

// ---------------- channel attention scale s (deterministic partial-sum reduce) ---------------
__global__ void k_s(const float* __restrict__ caw, const float* __restrict__ cab){
    __shared__ float gg[Bsz*Cdim];
    int tid = threadIdx.x;  // 384
    const float* p = g_gappart + (size_t)tid*512;
    float s = 0.f;
    for (int i=0;i<512;i++) s += p[i];
    gg[tid] = s*(1.f/HW);
    __syncthreads();
    int b = tid/Cdim, o = tid%Cdim;
    float acc = cab[o];
    for (int c=0;c<Cdim;c++) acc += gg[b*Cdim+c]*caw[o*Cdim+c];
    g_s[tid] = acc;
}

// ---------------- x1 = x + yattn*s, norm2, emit BHWC tokens for MLP ----------------
__global__ void k_addnorm2(const float* __restrict__ x,
                           const float* __restrict__ nw, const float* __restrict__ nb){
    __shared__ float tile[Cdim][33];
    __shared__ float red1[8][32], red2[8][32];
    __shared__ float s_mu[32], s_ri[32];
    __shared__ float s_w[Cdim], s_b[Cdim], s_sc[Cdim];
    int b = blockIdx.y;
    int p0 = blockIdx.x*32;
    int tid = threadIdx.x;
    if (tid < Cdim){ s_w[tid]=nw[tid]; s_b[tid]=nb[tid]; s_sc[tid]=g_s[b*Cdim+tid]; }
    __syncthreads();
    const float* xb = x + (size_t)b*CHW;
    const __nv_bfloat16* yb = g_yattn + (size_t)b*CHW;
    #pragma unroll
    for (int it=0; it<24; it++){
        int idx = it*256+tid;
        int c = idx>>5, p = idx&31;
        size_t off = (size_t)c*HW + p0+p;
        tile[c][p] = xb[off] + __bfloat162float(yb[off])*s_sc[c];
    }
    __syncthreads();
    int p = tid&31, g = tid>>5;
    float sum=0.f, sq=0.f;
    for (int c=g; c<Cdim; c+=8){ float v=tile[c][p]; sum+=v; sq+=v*v; }
    red1[g][p]=sum; red2[g][p]=sq;
    __syncthreads();
    if (g==0){
        float s=0.f,q=0.f;
        #pragma unroll
        for (int k=0;k<8;k++){ s+=red1[k][p]; q+=red2[k][p]; }
        float mu = s*(1.f/Cdim);
        float var = q*(1.f/Cdim) - mu*mu;
        s_mu[p]=mu; s_ri[p]=rsqrtf(var+1e-6f);
    }
    __syncthreads();
    #pragma unroll
    for (int it=0; it<24; it++){
        int idx = it*256+tid;
        int pp = idx/192, c = idx%192;
        float v = (tile[c][pp]-s_mu[pp])*s_ri[pp]*s_w[c]+s_b[c];
        g_t[((size_t)b*HW + p0+pp)*Cdim + c] = __float2bfloat16(v);
    }
}

// ---------------- launch ----------------
extern "C" void kernel_launch(void* const* d_in, const int* in_sizes, int n_in,
                              void* d_out, int out_size){
    const float* x    = (const float*)d_in[0];
    const float* n1w  = (const float*)d_in[1];
    const float* n1b  = (const float*)d_in[2];
    const float* qkvw = (const float*)d_in[3];
    const float* qkvb = (const float*)d_in[4];
    const float* projw= (const float*)d_in[5];
    const float* projb= (const float*)d_in[6];
    const float* rpb  = (const float*)d_in[7];
    const float* caw  = (const float*)d_in[8];
    const float* cab  = (const float*)d_in[9];
    const float* n2w  = (const float*)d_in[10];
    const float* n2b  = (const float*)d_in[11];
    const float* fc1w = (const float*)d_in[12];
    const float* fc1b = (const float*)d_in[13];
    const float* fc2w = (const float*)d_in[14];
    const float* fc2b = (const float*)d_in[15];
    float* out = (float*)d_out;

    const int smG192 = 192*80*2 + 2*128*80*2;   // 71680
    const int smG384 = 384*80*2 + 2*128*80*2;   // 102400
    static bool attr_done = false;
    if (!attr_done){
        cudaFuncSetAttribute(k_attn,        cudaFuncAttributeMaxDynamicSharedMemorySize, ATT_SM);
        cudaFuncSetAttribute(k_gemm_qkv,    cudaFuncAttributeMaxDynamicSharedMemorySize, smG192);
        cudaFuncSetAttribute(k_gemm_proj_f, cudaFuncAttributeMaxDynamicSharedMemorySize, smG192);
        cudaFuncSetAttribute(k_gemm_fc1,    cudaFuncAttributeMaxDynamicSharedMemorySize, smG192);
        cudaFuncSetAttribute(k_gemm_fc2_f,  cudaFuncAttributeMaxDynamicSharedMemorySize, smG384);
        attr_done = true;
    }

    k_conv_all  <<<(Cdim*C3+255)/256, 256>>>(qkvw, qkvb, projw, fc1w, fc2w);
    k_norm1_roll<<<dim3(HW/32, Bsz), 256>>>(x, n1w, n1b);
    k_win_gather<<<NWIN, 256>>>();
    k_gemm_qkv  <<<dim3(NTOK/128, C3/64),   256, smG192>>>();
    k_attn      <<<NWIN, 256, ATT_SM>>>(rpb);
    k_gemm_proj_f<<<dim3(NTOK/128, Cdim/64),256, smG192>>>(projb);
    k_s         <<<1, 384>>>(caw, cab);
    k_addnorm2  <<<dim3(HW/32, Bsz), 256>>>(x, n2w, n2b);
    k_gemm_fc1  <<<dim3(NTOK/128, HID/64),  256, smG192>>>(fc1b);
    k_gemm_fc2_f<<<dim3(NTOK/128, Cdim/64), 256, smG384>>>(fc2b, x, out);
}

// round 11
// speedup vs baseline: 1.0640x; 1.0640x over previous
#include <cuda_runtime.h>
#include <cuda_bf16.h>
#include <mma.h>

using namespace nvcuda;

#define Bsz   2
#define Cdim  192
#define Hdim  256
#define Wdim  256
#define HW    65536
#define CHW   12582912
#define NHEAD 6
#define HD    32
#define NTOK  131072
#define C3    576
#define HID   384
#define NWIN  2048

// ---------------- scratch (device globals; no allocation allowed) ----------------
__device__ __nv_bfloat16 g_roll[(size_t)Bsz*CHW];
__device__ __nv_bfloat16 g_win[(size_t)NTOK*Cdim];
__device__ __nv_bfloat16 g_qkv[(size_t)NTOK*C3];
__device__ __nv_bfloat16 g_attnout[(size_t)NTOK*Cdim];
__device__ __nv_bfloat16 g_yattn[(size_t)Bsz*CHW];
__device__ float         g_gappart[(size_t)Bsz*Cdim*512];
__device__ float         g_s[Bsz*Cdim];
__device__ __nv_bfloat16 g_t[(size_t)NTOK*Cdim];
__device__ __nv_bfloat16 g_h[(size_t)NTOK*HID];
__device__ __nv_bfloat16 g_wqkv[Cdim*C3];
__device__ float         g_bqkv[C3];
__device__ __nv_bfloat16 g_wproj[Cdim*Cdim];
__device__ __nv_bfloat16 g_wfc1[Cdim*HID];
__device__ __nv_bfloat16 g_wfc2[HID*Cdim];

// ---------------- all weight conversions in one kernel (scale folded into q cols) -------------
__global__ void k_conv_all(const float* __restrict__ qw, const float* __restrict__ qb,
                           const float* __restrict__ pw, const float* __restrict__ f1,
                           const float* __restrict__ f2){
    int i = blockIdx.x*256 + threadIdx.x;
    const float sc = 0.17677669529663687f; // 32^-0.5
    if (i < Cdim*C3){
        int o = i % C3;
        float f = qw[i];
        if (o < Cdim) f *= sc;
        g_wqkv[i] = __float2bfloat16(f);
    }
    if (i < C3){
        float f = qb[i];
        if (i < Cdim) f *= sc;
        g_bqkv[i] = f;
    }
    if (i < Cdim*Cdim) g_wproj[i] = __float2bfloat16(pw[i]);
    if (i < Cdim*HID)  g_wfc1[i]  = __float2bfloat16(f1[i]);
    if (i < HID*Cdim)  g_wfc2[i]  = __float2bfloat16(f2[i]);
}

// ---------------- norm1 (over C per pixel) fused with the "buggy" flat roll ----------------
__global__ void k_norm1_roll(const float* __restrict__ x,
                             const float* __restrict__ nw, const float* __restrict__ nb){
    __shared__ float tile[Cdim][33];
    __shared__ float red1[8][32], red2[8][32];
    __shared__ float s_mu[32], s_ri[32];
    __shared__ float s_w[Cdim], s_b[Cdim];
    int b = blockIdx.y;
    int p0 = blockIdx.x * 32;
    const float* xb = x + (size_t)b*CHW;
    int tid = threadIdx.x;
    if (tid < Cdim){ s_w[tid]=nw[tid]; s_b[tid]=nb[tid]; }
    #pragma unroll
    for (int it=0; it<24; it++){
        int idx = it*256+tid;
        int c = idx>>5, p = idx&31;
        tile[c][p] = xb[(size_t)c*HW + p0 + p];
    }
    __syncthreads();
    int p = tid&31, g = tid>>5;
    float sum=0.f, sq=0.f;
    for (int c=g; c<Cdim; c+=8){ float v=tile[c][p]; sum+=v; sq+=v*v; }
    red1[g][p]=sum; red2[g][p]=sq;
    __syncthreads();
    if (g==0){
        float s=0.f,q=0.f;
        #pragma unroll
        for (int k=0;k<8;k++){ s+=red1[k][p]; q+=red2[k][p]; }
        float mu = s*(1.f/Cdim);
        float var = q*(1.f/Cdim) - mu*mu;
        s_mu[p]=mu; s_ri[p]=rsqrtf(var+1e-6f);
    }
    __syncthreads();
    __nv_bfloat16* rb = g_roll + (size_t)b*CHW;
    #pragma unroll
    for (int it=0; it<24; it++){
        int idx = it*256+tid;
        int c = idx>>5, pp = idx&31;
        float v = (tile[c][pp]-s_mu[pp])*s_ri[pp]*s_w[c]+s_b[c];
        int f = c*HW + p0 + pp;
        int i = f/49152; int r = f - i*49152; int j = r/192; int k = r - j*192;
        int t = ((i-4)&255)*49152 + ((j-4)&255)*192 + k;
        rb[t] = __float2bfloat16(v);
    }
}

// ---------------- window partition: rolled BCHW -> (win, n, c) tokens ----------------
__global__ void k_win_gather(){
    __shared__ __nv_bfloat16 s[96][66];
    int wi = blockIdx.x; int tid = threadIdx.x;
    int b = wi>>10, gh=(wi&1023)>>5, gw=wi&31;
    const __nv_bfloat16* rb = g_roll + (size_t)b*CHW;
    size_t base = (size_t)(gh*8)*256 + gw*8;
    for (int chunk=0; chunk<2; chunk++){
        int c0 = chunk*96;
        #pragma unroll
        for (int it=0; it<24; it++){
            int idx = it*256+tid;
            int cl = idx>>6, n = idx&63;
            s[cl][n] = rb[(size_t)(c0+cl)*HW + base + (n>>3)*256 + (n&7)];
        }
        __syncthreads();
        #pragma unroll
        for (int it=0; it<24; it++){
            int idx = it*256+tid;
            int n = idx/96, cl = idx%96;
            g_win[((size_t)wi*64+n)*Cdim + c0 + cl] = s[cl][n];
        }
        __syncthreads();
    }
}

// ---------------- GEMM mainloop: 128x64 tile, resident B, double-buffered A -------------------
// ldm = 72 bf16 (144B row stride): LDSM bank-start = 4r mod 32 -> conflict-free.
template<int K, int N>
__device__ __forceinline__ float* gemm_main(const __nv_bfloat16* __restrict__ A,
                                            const __nv_bfloat16* __restrict__ Bm){
    extern __shared__ __align__(16) char sm[];
    __nv_bfloat16* Bs = (__nv_bfloat16*)sm;                       // [K][72]
    __nv_bfloat16* As = (__nv_bfloat16*)(sm + (size_t)K*72*2);    // [2][128][72]
    float*         Cs = (float*)(sm + (size_t)K*72*2);            // [128][68] (aliases As)
    const int tid = threadIdx.x;
    const int m0 = blockIdx.x*128, n0 = blockIdx.y*64;
    const int warp = tid>>5, wr = warp>>1, wc = warp&1;

    #pragma unroll
    for (int it=0; it<K/32; it++){
        int idx = it*256+tid;
        int row = idx>>3, u = idx&7;
        *(uint4*)&Bs[row*72 + u*8] = *(const uint4*)&Bm[(size_t)row*N + n0 + u*8];
    }
    auto loadA = [&](int c, int buf){
        #pragma unroll
        for (int it=0; it<4; it++){
            int idx = it*256+tid;
            int row = idx>>3, u = idx&7;
            *(uint4*)&As[(size_t)(buf*128+row)*72 + u*8] =
                *(const uint4*)&A[(size_t)(m0+row)*K + c*64 + u*8];
        }
    };
    loadA(0,0);
    wmma::fragment<wmma::accumulator,16,16,16,float> acc[2][2];
    #pragma unroll
    for (int i=0;i<2;i++)
        #pragma unroll
        for (int j=0;j<2;j++) wmma::fill_fragment(acc[i][j], 0.f);
    __syncthreads();

    constexpr int NC = K/64;
    #pragma unroll
    for (int c=0;c<NC;c++){
        if (c+1 < NC) loadA(c+1, (c+1)&1);
        int buf = c&1;
        #pragma unroll
        for (int kk=0;kk<64;kk+=16){
            wmma::fragment<wmma::matrix_a,16,16,16,__nv_bfloat16,wmma::row_major> af[2];
            wmma::fragment<wmma::matrix_b,16,16,16,__nv_bfloat16,wmma::row_major> bf[2];
            #pragma unroll
            for (int i=0;i<2;i++) wmma::load_matrix_sync(af[i], &As[(size_t)(buf*128+wr*32+i*16)*72 + kk], 72);
            #pragma unroll
            for (int j=0;j<2;j++) wmma::load_matrix_sync(bf[j], &Bs[(size_t)(c*64+kk)*72 + wc*32+j*16], 72);
            #pragma unroll
            for (int i=0;i<2;i++)
                #pragma unroll
                for (int j=0;j<2;j++)
                    wmma::mma_sync(acc[i][j], af[i], bf[j], acc[i][j]);
        }
        __syncthreads();
    }
    #pragma unroll
    for (int i=0;i<2;i++)
        #pragma unroll
        for (int j=0;j<2;j++)
            wmma::store_matrix_sync(&Cs[(size_t)(wr*32+i*16)*68 + wc*32+j*16], acc[i][j], 68, wmma::mem_row_major);
    __syncthreads();
    return Cs;
}

// qkv: plain bf16 epilogue
__global__ void __launch_bounds__(256) k_gemm_qkv(){
    float* Cs = gemm_main<Cdim,C3>(g_win, g_wqkv);
    const int tid = threadIdx.x;
    const int m0 = blockIdx.x*128, n0 = blockIdx.y*64;
    #pragma unroll
    for (int it=0; it<32; it++){
        int idx = it*256+tid;
        int r = idx>>6, cc = idx&63;
        float v = Cs[(size_t)r*68+cc] + g_bqkv[n0+cc];
        g_qkv[(size_t)(m0+r)*C3 + n0 + cc] = __float2bfloat16(v);
    }
}

// fc1: gelu epilogue
__global__ void __launch_bounds__(256) k_gemm_fc1(const float* __restrict__ bias){
    float* Cs = gemm_main<Cdim,HID>(g_t, g_wfc1);
    const int tid = threadIdx.x;
    const int m0 = blockIdx.x*128, n0 = blockIdx.y*64;
    #pragma unroll
    for (int it=0; it<32; it++){
        int idx = it*256+tid;
        int r = idx>>6, cc = idx&63;
        float v = Cs[(size_t)r*68+cc] + bias[n0+cc];
        v = 0.5f*v*(1.f+erff(v*0.70710678118654752f));
        g_h[(size_t)(m0+r)*HID + n0 + cc] = __float2bfloat16(v);
    }
}

// proj: fused window-reverse scatter into BCHW yattn + deterministic gap partials
__global__ void __launch_bounds__(256) k_gemm_proj_f(const float* __restrict__ bias){
    float* Cs = gemm_main<Cdim,Cdim>(g_attnout, g_wproj);
    __shared__ float sgap[4][64];
    const int tid = threadIdx.x;
    const int m0 = blockIdx.x*128, n0 = blockIdx.y*64;
    const int w0 = m0/64;                 // first window of the pair
    const int b  = w0>>10;
    const int lane16 = tid&15, w = lane16>>3, q = lane16&7, grp16 = tid>>4;
    {
        int wi = w0 + w;
        int gh = (wi&1023)>>5, gw = wi&31;
        size_t pixbase = (size_t)b*CHW + (size_t)gh*2048 + gw*8 + q;
        #pragma unroll
        for (int it=0; it<32; it++){
            int combo = it*16 + grp16;      // 0..511 = cc*8 + i
            int cc = combo>>3, i = combo&7;
            int r = w*64 + i*8 + q;
            float v = Cs[(size_t)r*68+cc] + bias[n0+cc];
            g_yattn[pixbase + (size_t)(n0+cc)*HW + i*256] = __float2bfloat16(v);
        }
    }
    {
        int cc = tid&63, grp = tid>>6;
        float s = 0.f;
        float bb = bias[n0+cc];
        #pragma unroll
        for (int k=0;k<32;k++){
            int r = grp*32+k;
            s += __bfloat162float(__float2bfloat16(Cs[(size_t)r*68+cc] + bb));
        }
        sgap[grp][cc] = s;
        __syncthreads();
        if (tid < 64){
            float t = sgap[0][tid]+sgap[1][tid]+sgap[2][tid]+sgap[3][tid];
            g_gappart[(size_t)(b*Cdim + n0 + tid)*512 + (blockIdx.x & 511)] = t;
        }
    }
}

// fc2: fused final residual  out = x + yattn*s + fc2(h)
__global__ void __launch_bounds__(256) k_gemm_fc2_f(const float* __restrict__ bias,
                                                    const float* __restrict__ x,
                                                    float* __restrict__ out){
    float* Cs = gemm_main<HID,Cdim>(g_h, g_wfc2);
    __shared__ float s_sc[64];
    const int tid = threadIdx.x;
    const int m0 = blockIdx.x*128, n0 = blockIdx.y*64;
    const int b = m0>>16, p0 = m0&65535;
    if (tid < 64) s_sc[tid] = g_s[b*Cdim + n0 + tid];
    __syncthreads();
    #pragma unroll
    for (int it=0; it<32; it++){
        int idx = it*256+tid;
        int cc = idx>>7, pp = idx&127;
        float v = Cs[(size_t)pp*68+cc] + bias[n0+cc];
        size_t off = (size_t)b*CHW + (size_t)(n0+cc)*HW + p0 + pp;
        float y = __bfloat162float(g_yattn[off]);
        out[off] = x[off] + y*s_sc[cc] + v;
    }
}

// ---------------- fused window attention, WMMA: 2 blocks/SM (112.5KB smem) ----------------
#define LDQ 584
#define ATT_SS  74752
#define ATT_RPB 109568
#define ATT_CLS 112272
#define ATT_SM  112528
__global__ void __launch_bounds__(256) k_attn(const float* __restrict__ rpb){
    extern __shared__ __align__(16) char sm[];
    __nv_bfloat16* sQ   = (__nv_bfloat16*)sm;                   // [64][584]
    float*         sS   = (float*)(sm + ATT_SS);                // [8][16*68]  (P aliases this)
    __nv_bfloat16* sRpb = (__nv_bfloat16*)(sm + ATT_RPB);       // [6*225]
    int*           sCls = (int*)(sm + ATT_CLS);                 // [64]
    int wi = blockIdx.x;
    int tid = threadIdx.x, warp = tid>>5, lane = tid&31;
    int gh = (wi & 1023) >> 5, gw = wi & 31;

    const __nv_bfloat16* qkvb = g_qkv + (size_t)wi*64*C3;
    #pragma unroll
    for (int it=0; it<18; it++){
        int idx = it*256+tid;
        int row = idx/72, u = idx%72;
        *(uint4*)&sQ[row*LDQ + u*8] = *(const uint4*)&qkvb[(size_t)row*C3 + u*8];
    }
    for (int i=tid; i<NHEAD*225; i+=256){
        int h = i/225, p = i%225;
        sRpb[h*225+p] = __float2bfloat16(rpb[p*NHEAD + h]);
    }
    if (tid < 64){
        int i = tid>>3, j = tid&7;
        int hg = gh*8+i, wg = gw*8+j;
        int rh = hg < 248 ? 0 : (hg < 252 ? 1 : 2);
        int rw = wg < 248 ? 0 : (wg < 252 ? 1 : 2);
        sCls[tid] = rh*3+rw;
    }
    __syncthreads();

    #pragma unroll
    for (int r=0; r<3; r++){
        int task = warp + 8*r;            // 0..23
        int h = task>>2, strip = task&3, n0 = strip*16;
        float*         Sw = sS + warp*16*68;
        __nv_bfloat16* Pw = (__nv_bfloat16*)Sw;     // alias: reads complete before writes
        // ---- S = Q Kt (16x64) ----
        wmma::fragment<wmma::accumulator,16,16,16,float> acc[4];
        #pragma unroll
        for (int j=0;j<4;j++) wmma::fill_fragment(acc[j], 0.f);
        #pragma unroll
        for (int kk=0; kk<32; kk+=16){
            wmma::fragment<wmma::matrix_a,16,16,16,__nv_bfloat16,wmma::row_major> aq;
            wmma::load_matrix_sync(aq, &sQ[(size_t)n0*LDQ + h*HD + kk], LDQ);
            #pragma unroll
            for (int j=0;j<4;j++){
                wmma::fragment<wmma::matrix_b,16,16,16,__nv_bfloat16,wmma::col_major> bk;
                wmma::load_matrix_sync(bk, &sQ[(size_t)(j*16)*LDQ + Cdim + h*HD + kk], LDQ);
                wmma::mma_sync(acc[j], aq, bk, acc[j]);
            }
        }
        #pragma unroll
        for (int j=0;j<4;j++)
            wmma::store_matrix_sync(&Sw[j*16], acc[j], 68, wmma::mem_row_major);
        __syncwarp();
        // ---- softmax with rpb bias + shift mask (lane: one row half) ----
        {
            int row = lane>>1, half = (lane&1)*32;
            int n = n0+row, ni = n>>3, nj = n&7;
            int cn = sCls[n];
            const __nv_bfloat16* rh = sRpb + h*225;
            float e[32]; float mx = -1e30f;
            #pragma unroll
            for (int c=0;c<32;c++){
                int m = half+c;
                float v = Sw[row*68+m] + __bfloat162float(rh[(ni-(m>>3)+7)*15 + (nj-(m&7)+7)]);
                if (cn != sCls[m]) v -= 100.f;
                e[c]=v; mx = fmaxf(mx, v);
            }
            mx = fmaxf(mx, __shfl_xor_sync(0xffffffffu, mx, 1));   // warp-sync: all reads done
            float sum = 0.f;
            #pragma unroll
            for (int c=0;c<32;c++){ e[c] = __expf(e[c]-mx); sum += e[c]; }
            sum += __shfl_xor_sync(0xffffffffu, sum, 1);
            float inv = 1.f/sum;
            __syncwarp();
            #pragma unroll
            for (int c=0;c<32;c++) Pw[row*72+half+c] = __float2bfloat16(e[c]*inv);
        }
        __syncwarp();
        // ---- out = P V (16x32) ----
        wmma::fragment<wmma::accumulator,16,16,16,float> acc2[2];
        #pragma unroll
        for (int j=0;j<2;j++) wmma::fill_fragment(acc2[j], 0.f);
        #pragma unroll
        for (int k4=0;k4<4;k4++){
            wmma::fragment<wmma::matrix_a,16,16,16,__nv_bfloat16,wmma::row_major> ap;
            wmma::load_matrix_sync(ap, &Pw[k4*16], 72);
            #pragma unroll
            for (int j=0;j<2;j++){
                wmma::fragment<wmma::matrix_b,16,16,16,__nv_bfloat16,wmma::row_major> bv;
                wmma::load_matrix_sync(bv, &sQ[(size_t)(k4*16)*LDQ + 2*Cdim + h*HD + j*16], LDQ);
                wmma::mma_sync(acc2[j], ap, bv, acc2[j]);
            }
        }
        __syncwarp();     // all Pw reads done before overwriting region
        #pragma unroll
        for (int j=0;j<2;j++)
            wmma::store_matrix_sync(&Sw[j*16], acc2[j], 36, wmma::mem_row_major);
        __syncwarp();
        {
            int row = lane>>1, halfo = (lane&1)*16;
            __nv_bfloat16* op = g_attnout + ((size_t)(wi*64 + n0+row))*Cdim + h*HD + halfo;
            #pragma unroll
            for (int c=0;c<16;c++) op[c] = __float2bfloat16(Sw[row*36 + halfo + c]);
        }
        __syncwarp();
    }
}

// ---------------- channel attention scale s (deterministic partial-sum reduce) ---------------
__global__ void k_s(const float* __restrict__ caw, const float* __restrict__ cab){
    __shared__ float gg[Bsz*Cdim];
    int tid = threadIdx.x;  // 384
    const float* p = g_gappart + (size_t)tid*512;
    float s = 0.f;
    for (int i=0;i<512;i++) s += p[i];
    gg[tid] = s*(1.f/HW);
    __syncthreads();
    int b = tid/Cdim, o = tid%Cdim;
    float acc = cab[o];
    for (int c=0;c<Cdim;c++) acc += gg[b*Cdim+c]*caw[o*Cdim+c];
    g_s[tid] = acc;
}

// ---------------- x1 = x + yattn*s, norm2, emit BHWC tokens for MLP ----------------
__global__ void k_addnorm2(const float* __restrict__ x,
                           const float* __restrict__ nw, const float* __restrict__ nb){
    __shared__ float tile[Cdim][33];
    __shared__ float red1[8][32], red2[8][32];
    __shared__ float s_mu[32], s_ri[32];
    __shared__ float s_w[Cdim], s_b[Cdim], s_sc[Cdim];
    int b = blockIdx.y;
    int p0 = blockIdx.x*32;
    int tid = threadIdx.x;
    if (tid < Cdim){ s_w[tid]=nw[tid]; s_b[tid]=nb[tid]; s_sc[tid]=g_s[b*Cdim+tid]; }
    __syncthreads();
    const float* xb = x + (size_t)b*CHW;
    const __nv_bfloat16* yb = g_yattn + (size_t)b*CHW;
    #pragma unroll
    for (int it=0; it<24; it++){
        int idx = it*256+tid;
        int c = idx>>5, p = idx&31;
        size_t off = (size_t)c*HW + p0+p;
        tile[c][p] = xb[off] + __bfloat162float(yb[off])*s_sc[c];
    }
    __syncthreads();
    int p = tid&31, g = tid>>5;
    float sum=0.f, sq=0.f;
    for (int c=g; c<Cdim; c+=8){ float v=tile[c][p]; sum+=v; sq+=v*v; }
    red1[g][p]=sum; red2[g][p]=sq;
    __syncthreads();
    if (g==0){
        float s=0.f,q=0.f;
        #pragma unroll
        for (int k=0;k<8;k++){ s+=red1[k][p]; q+=red2[k][p]; }
        float mu = s*(1.f/Cdim);
        float var = q*(1.f/Cdim) - mu*mu;
        s_mu[p]=mu; s_ri[p]=rsqrtf(var+1e-6f);
    }
    __syncthreads();
    #pragma unroll
    for (int it=0; it<24; it++){
        int idx = it*256+tid;
        int pp = idx/192, c = idx%192;
        float v = (tile[c][pp]-s_mu[pp])*s_ri[pp]*s_w[c]+s_b[c];
        g_t[((size_t)b*HW + p0+pp)*Cdim + c] = __float2bfloat16(v);
    }
}

// ---------------- launch ----------------
extern "C" void kernel_launch(void* const* d_in, const int* in_sizes, int n_in,
                              void* d_out, int out_size){
    const float* x    = (const float*)d_in[0];
    const float* n1w  = (const float*)d_in[1];
    const float* n1b  = (const float*)d_in[2];
    const float* qkvw = (const float*)d_in[3];
    const float* qkvb = (const float*)d_in[4];
    const float* projw= (const float*)d_in[5];
    const float* projb= (const float*)d_in[6];
    const float* rpb  = (const float*)d_in[7];
    const float* caw  = (const float*)d_in[8];
    const float* cab  = (const float*)d_in[9];
    const float* n2w  = (const float*)d_in[10];
    const float* n2b  = (const float*)d_in[11];
    const float* fc1w = (const float*)d_in[12];
    const float* fc1b = (const float*)d_in[13];
    const float* fc2w = (const float*)d_in[14];
    const float* fc2b = (const float*)d_in[15];
    float* out = (float*)d_out;

    const int smG192 = 192*72*2 + 2*128*72*2;   // 64512
    const int smG384 = 384*72*2 + 2*128*72*2;   // 92160
    static bool attr_done = false;
    if (!attr_done){
        cudaFuncSetAttribute(k_attn,        cudaFuncAttributeMaxDynamicSharedMemorySize, ATT_SM);
        cudaFuncSetAttribute(k_gemm_qkv,    cudaFuncAttributeMaxDynamicSharedMemorySize, smG192);
        cudaFuncSetAttribute(k_gemm_proj_f, cudaFuncAttributeMaxDynamicSharedMemorySize, smG192);
        cudaFuncSetAttribute(k_gemm_fc1,    cudaFuncAttributeMaxDynamicSharedMemorySize, smG192);
        cudaFuncSetAttribute(k_gemm_fc2_f,  cudaFuncAttributeMaxDynamicSharedMemorySize, smG384);
        attr_done = true;
    }

    k_conv_all  <<<(Cdim*C3+255)/256, 256>>>(qkvw, qkvb, projw, fc1w, fc2w);
    k_norm1_roll<<<dim3(HW/32, Bsz), 256>>>(x, n1w, n1b);
    k_win_gather<<<NWIN, 256>>>();
    k_gemm_qkv  <<<dim3(NTOK/128, C3/64),   256, smG192>>>();
    k_attn      <<<NWIN, 256, ATT_SM>>>(rpb);
    k_gemm_proj_f<<<dim3(NTOK/128, Cdim/64),256, smG192>>>(projb);
    k_s         <<<1, 384>>>(caw, cab);
    k_addnorm2  <<<dim3(HW/32, Bsz), 256>>>(x, n2w, n2b);
    k_gemm_fc1  <<<dim3(NTOK/128, HID/64),  256, smG192>>>(fc1b);
    k_gemm_fc2_f<<<dim3(NTOK/128, Cdim/64), 256, smG384>>>(fc2b, x, out);
}